// round 13
// baseline (speedup 1.0000x reference)
#include <cuda_runtime.h>
#include <cstdint>

#define TPB    512
#define TILE_M 128
#define MM     256
#define KK     64
#define ZST    72          // stride ≡ 8 (mod 32) -> conflict-free LDS.64 frags
#define BST    72

// smem layout (float offsets)
#define F_BHI  0
#define F_BLO  (F_BHI + MM * BST)        // 18432
#define F_ZHI  (F_BLO + MM * BST)        // 36864
#define F_ZLO  (F_ZHI + TILE_M * ZST)    // 46080
#define F_B    (F_ZLO + TILE_M * ZST)    // 55296
#define F_PAT  (F_B + MM)                // 55552
#define F_PIV  (F_PAT + MM)              // 55808
#define F_C    (F_PIV + KK)              // 55872
#define F_PSA  (F_C + TILE_M)            // 56000 (4 n-warps x 128 rows)
#define F_PND  (F_PSA + 4 * TILE_M)      // 56512
#define SMEM_FLOATS (F_PND + 4 * TILE_M) // 57024 -> 228096 B

extern __shared__ float sm[];

// k -> stored position: fragment pair (k, k+4) becomes adjacent words
__device__ __forceinline__ int kpos(int k)
{
    return (k & ~7) | ((k & 3) << 1) | ((k >> 2) & 1);
}

// tf32 split: hi = rna(x), lo = rna(x - hi)
__device__ __forceinline__ void split_tf32(float x, uint32_t& hi, uint32_t& lo)
{
    asm("cvt.rna.tf32.f32 %0, %1;" : "=r"(hi) : "f"(x));
    float r = x - __uint_as_float(hi);
    asm("cvt.rna.tf32.f32 %0, %1;" : "=r"(lo) : "f"(r));
}

// m16n8k8 tf32 MMA (sm_80 PTX -> legacy HMMA on sm_103)
__device__ __forceinline__ void mma8(float& c0, float& c1, float& c2, float& c3,
                                     uint32_t a0, uint32_t a1, uint32_t a2, uint32_t a3,
                                     uint32_t b0, uint32_t b1)
{
    asm("mma.sync.aligned.m16n8k8.row.col.f32.tf32.tf32.f32 "
        "{%0,%1,%2,%3}, {%4,%5,%6,%7}, {%8,%9}, {%0,%1,%2,%3};"
        : "+f"(c0), "+f"(c1), "+f"(c2), "+f"(c3)
        : "r"(a0), "r"(a1), "r"(a2), "r"(a3), "r"(b0), "r"(b1));
}

// division-free running argmax of alpha = sa/nd
__device__ __forceinline__ void upd(float s, float bcol, float pcol,
                                    float& bsa, float& bnd)
{
    const float sa = s - bcol;
    const float nd = fmaxf(s - pcol, 1e-9f);
    const bool take = (sa >= 0.0f) && (sa * bnd > bsa * nd);
    bsa = take ? sa : bsa;
    bnd = take ? nd : bnd;
}

__global__ void __launch_bounds__(TPB, 1)
constrain_kernel(const float* __restrict__ z,
                 const float* __restrict__ pivot,
                 const float* __restrict__ At,
                 const float* __restrict__ b,
                 float* __restrict__ out,
                 int ntiles)
{
    const int tid = threadIdx.x;
    const int wid = tid >> 5;
    const int lid = tid & 31;
    const int grp = lid >> 2;          // groupID  (0..7)
    const int tig = lid & 3;           // thread-in-group (0..3)
    const int wm  = wid & 3;           // m-warp (0..3): rows wm*32..+31
    const int wn  = wid >> 2;          // n-warp (0..3): cols wn*64..+63
    const int m0  = wm * 32;

    uint32_t* smu = reinterpret_cast<uint32_t*>(sm);

    // ---- stage B = At^T split (once): B[n][kpos], n-major, stride 72 ----
    #pragma unroll 1
    for (int idx = tid; idx < KK * MM; idx += TPB) {
        const int d = idx >> 8;        // k
        const int n = idx & 255;       // coalesced in n
        uint32_t hi, lo;
        split_tf32(At[idx], hi, lo);
        const int p = n * BST + kpos(d);
        smu[F_BHI + p] = hi;
        smu[F_BLO + p] = lo;
    }
    if (tid < KK) sm[F_PIV + tid] = pivot[tid];
    if (tid < MM) sm[F_B + tid] = b[tid];
    __syncthreads();

    // ---- pAt = pivot @ At (fp32, from global; coalesced per d) ----
    if (tid < MM) {
        float a = 0.0f;
        #pragma unroll
        for (int d = 0; d < KK; ++d)
            a = fmaf(sm[F_PIV + d], At[d * MM + tid], a);
        sm[F_PAT + tid] = a;
    }

    // rows this thread reduces: m0+grp, +8, +16, +24
    const int ar0 = (m0 + grp) * ZST;
    const int ar1 = (m0 + 8 + grp) * ZST;
    const int ar2 = (m0 + 16 + grp) * ZST;
    const int ar3 = (m0 + 24 + grp) * ZST;

    // z staging slots: i = tid + q*TPB -> row = i>>4, kq = i&15 (float4 along k)
    // permuted store: float4 at kq covers one half of k-group (kq>>1);
    // positions = group*8 + (kq&1) + {0,2,4,6}
    float4 zr[4];

    {
        const float4* zg4 = reinterpret_cast<const float4*>(z) +
                            (size_t)blockIdx.x * TILE_M * (KK / 4);
        #pragma unroll
        for (int q = 0; q < 4; ++q) {
            const int i   = tid + q * TPB;
            const int row = i >> 4;
            const int kq  = i & 15;
            zr[q] = zg4[i];
            uint32_t h0, l0, h1, l1, h2, l2, h3, l3;
            split_tf32(zr[q].x, h0, l0); split_tf32(zr[q].y, h1, l1);
            split_tf32(zr[q].z, h2, l2); split_tf32(zr[q].w, h3, l3);
            const int base = row * ZST + (kq >> 1) * 8 + (kq & 1);
            smu[F_ZHI + base + 0] = h0;  smu[F_ZLO + base + 0] = l0;
            smu[F_ZHI + base + 2] = h1;  smu[F_ZLO + base + 2] = l1;
            smu[F_ZHI + base + 4] = h2;  smu[F_ZLO + base + 4] = l2;
            smu[F_ZHI + base + 6] = h3;  smu[F_ZLO + base + 6] = l3;
        }
    }
    __syncthreads();

    for (int t = blockIdx.x; t < ntiles; t += gridDim.x) {
        const int tn = t + gridDim.x;

        // ---- prefetch next tile's z into registers ----
        float4 zf[4];
        if (tn < ntiles) {
            const float4* zg4 = reinterpret_cast<const float4*>(z) +
                                (size_t)tn * TILE_M * (KK / 4);
            #pragma unroll
            for (int q = 0; q < 4; ++q)
                zf[q] = zg4[tid + q * TPB];
        }

        float bsa[4] = {0.0f, 0.0f, 0.0f, 0.0f};
        float bnd[4] = {1.0f, 1.0f, 1.0f, 1.0f};

        #pragma unroll 1
        for (int nci = 0; nci < 2; ++nci) {
            const int nc = nci ^ (wm & 1);     // de-convoy: odd m-warps reversed
            const int nbase = wn * 64 + nc * 32;

            float C[4][8];
            #pragma unroll
            for (int ns = 0; ns < 4; ++ns)
                #pragma unroll
                for (int r = 0; r < 8; ++r) C[ns][r] = 0.0f;

            #pragma unroll 1
            for (int ks = 0; ks < 8; ++ks) {
                const int kb = ks * 8 + tig * 2;   // permuted pair (k0, k0+4)

                const uint2 ah_0 = *reinterpret_cast<const uint2*>(smu + F_ZHI + ar0 + kb);
                const uint2 ah_1 = *reinterpret_cast<const uint2*>(smu + F_ZHI + ar1 + kb);
                const uint2 ah_2 = *reinterpret_cast<const uint2*>(smu + F_ZHI + ar2 + kb);
                const uint2 ah_3 = *reinterpret_cast<const uint2*>(smu + F_ZHI + ar3 + kb);
                const uint2 al_0 = *reinterpret_cast<const uint2*>(smu + F_ZLO + ar0 + kb);
                const uint2 al_1 = *reinterpret_cast<const uint2*>(smu + F_ZLO + ar1 + kb);
                const uint2 al_2 = *reinterpret_cast<const uint2*>(smu + F_ZLO + ar2 + kb);
                const uint2 al_3 = *reinterpret_cast<const uint2*>(smu + F_ZLO + ar3 + kb);

                uint2 bh[4], bl[4];
                #pragma unroll
                for (int ns = 0; ns < 4; ++ns) {
                    const int bn = (nbase + ns * 8 + grp) * BST + kb;
                    bh[ns] = *reinterpret_cast<const uint2*>(smu + F_BHI + bn);
                    bl[ns] = *reinterpret_cast<const uint2*>(smu + F_BLO + bn);
                }

                // pass-major: same-C MMAs 8 apart
                #pragma unroll
                for (int ns = 0; ns < 4; ++ns) {   // hh
                    mma8(C[ns][0], C[ns][1], C[ns][2], C[ns][3],
                         ah_0.x, ah_1.x, ah_0.y, ah_1.y, bh[ns].x, bh[ns].y);
                    mma8(C[ns][4], C[ns][5], C[ns][6], C[ns][7],
                         ah_2.x, ah_3.x, ah_2.y, ah_3.y, bh[ns].x, bh[ns].y);
                }
                #pragma unroll
                for (int ns = 0; ns < 4; ++ns) {   // hl
                    mma8(C[ns][0], C[ns][1], C[ns][2], C[ns][3],
                         ah_0.x, ah_1.x, ah_0.y, ah_1.y, bl[ns].x, bl[ns].y);
                    mma8(C[ns][4], C[ns][5], C[ns][6], C[ns][7],
                         ah_2.x, ah_3.x, ah_2.y, ah_3.y, bl[ns].x, bl[ns].y);
                }
                #pragma unroll
                for (int ns = 0; ns < 4; ++ns) {   // lh
                    mma8(C[ns][0], C[ns][1], C[ns][2], C[ns][3],
                         al_0.x, al_1.x, al_0.y, al_1.y, bh[ns].x, bh[ns].y);
                    mma8(C[ns][4], C[ns][5], C[ns][6], C[ns][7],
                         al_2.x, al_3.x, al_2.y, al_3.y, bh[ns].x, bh[ns].y);
                }
            }

            // ---- epilogue for this 32-col chunk ----
            #pragma unroll
            for (int ns = 0; ns < 4; ++ns) {
                const int col0 = nbase + ns * 8 + 2 * tig;
                const float b0 = sm[F_B + col0],   b1 = sm[F_B + col0 + 1];
                const float p0 = sm[F_PAT + col0], p1 = sm[F_PAT + col0 + 1];
                upd(C[ns][0], b0, p0, bsa[0], bnd[0]);   // row grp
                upd(C[ns][1], b1, p1, bsa[0], bnd[0]);
                upd(C[ns][2], b0, p0, bsa[1], bnd[1]);   // row grp+8
                upd(C[ns][3], b1, p1, bsa[1], bnd[1]);
                upd(C[ns][4], b0, p0, bsa[2], bnd[2]);   // row grp+16
                upd(C[ns][5], b1, p1, bsa[2], bnd[2]);
                upd(C[ns][6], b0, p0, bsa[3], bnd[3]);   // row grp+24
                upd(C[ns][7], b1, p1, bsa[3], bnd[3]);
            }
        }

        // reduce across the 4 col-lanes (tig) via bfly xor 1, 2
        #pragma unroll
        for (int r = 0; r < 4; ++r) {
            #pragma unroll
            for (int off = 1; off <= 2; off <<= 1) {
                const float osa = __shfl_xor_sync(0xffffffffu, bsa[r], off);
                const float ond = __shfl_xor_sync(0xffffffffu, bnd[r], off);
                const bool tk = osa * bnd[r] > bsa[r] * ond;
                bsa[r] = tk ? osa : bsa[r];
                bnd[r] = tk ? ond : bnd[r];
            }
        }
        if (tig == 0) {
            const int base = wn * TILE_M + m0 + grp;
            sm[F_PSA + base]      = bsa[0];  sm[F_PND + base]      = bnd[0];
            sm[F_PSA + base + 8]  = bsa[1];  sm[F_PND + base + 8]  = bnd[1];
            sm[F_PSA + base + 16] = bsa[2];  sm[F_PND + base + 16] = bnd[2];
            sm[F_PSA + base + 24] = bsa[3];  sm[F_PND + base + 24] = bnd[3];
        }
        __syncthreads();   // (1) partials ready; all z-smem reads of tile t done

        // combine the four n-warp partials, one divide per row
        if (tid < TILE_M) {
            float fsa = sm[F_PSA + tid];
            float fnd = sm[F_PND + tid];
            #pragma unroll
            for (int h = 1; h < 4; ++h) {
                const float sa = sm[F_PSA + h * TILE_M + tid];
                const float nd = sm[F_PND + h * TILE_M + tid];
                const bool tk = sa * fnd > fsa * nd;
                fsa = tk ? sa : fsa;
                fnd = tk ? nd : fnd;
            }
            sm[F_C + tid] = fsa / fnd;
        }
        __syncthreads();   // (2) c ready

        // ---- store from registers: out = z + c*(pivot - z), exact z ----
        {
            float4* og4 = reinterpret_cast<float4*>(out) +
                          (size_t)t * TILE_M * (KK / 4);
            const float4* piv4 = reinterpret_cast<const float4*>(sm + F_PIV);
            #pragma unroll
            for (int q = 0; q < 4; ++q) {
                const int i   = tid + q * TPB;
                const int row = i >> 4;
                const int kq  = i & 15;
                const float cc = sm[F_C + row];
                const float4 zz = zr[q];
                const float4 pv = piv4[kq];
                float4 oo;
                oo.x = fmaf(cc, pv.x - zz.x, zz.x);
                oo.y = fmaf(cc, pv.y - zz.y, zz.y);
                oo.z = fmaf(cc, pv.z - zz.z, zz.z);
                oo.w = fmaf(cc, pv.w - zz.w, zz.w);
                og4[i] = oo;
            }
        }

        // ---- split prefetched z(t+1) into smem (safe after sync (1)) ----
        if (tn < ntiles) {
            #pragma unroll
            for (int q = 0; q < 4; ++q) {
                const int i   = tid + q * TPB;
                const int row = i >> 4;
                const int kq  = i & 15;
                uint32_t h0, l0, h1, l1, h2, l2, h3, l3;
                split_tf32(zf[q].x, h0, l0); split_tf32(zf[q].y, h1, l1);
                split_tf32(zf[q].z, h2, l2); split_tf32(zf[q].w, h3, l3);
                const int base = row * ZST + (kq >> 1) * 8 + (kq & 1);
                smu[F_ZHI + base + 0] = h0;  smu[F_ZLO + base + 0] = l0;
                smu[F_ZHI + base + 2] = h1;  smu[F_ZLO + base + 2] = l1;
                smu[F_ZHI + base + 4] = h2;  smu[F_ZLO + base + 4] = l2;
                smu[F_ZHI + base + 6] = h3;  smu[F_ZLO + base + 6] = l3;
            }
        }
        __syncthreads();   // (3) z smem for t+1 ready

        zr[0] = zf[0]; zr[1] = zf[1]; zr[2] = zf[2]; zr[3] = zf[3];
    }
}

extern "C" void kernel_launch(void* const* d_in, const int* in_sizes, int n_in,
                              void* d_out, int out_size)
{
    const float* z     = (const float*)d_in[0];  // [N, 64]
    const float* pivot = (const float*)d_in[1];  // [64]
    const float* At    = (const float*)d_in[2];  // [64, 256]
    const float* b     = (const float*)d_in[3];  // [256]
    float* out = (float*)d_out;                  // [N, 64]

    const int N = in_sizes[0] / KK;              // 262144
    const int ntiles = N / TILE_M;               // 2048
    const int smem_bytes = SMEM_FLOATS * (int)sizeof(float);  // 228096

    cudaFuncSetAttribute(constrain_kernel,
                         cudaFuncAttributeMaxDynamicSharedMemorySize, smem_bytes);

    int grid = 152;                              // persistent: 1 CTA/SM
    if (grid > ntiles) grid = ntiles;
    constrain_kernel<<<grid, TPB, smem_bytes>>>(z, pivot, At, b, out, ntiles);
}

// round 14
// speedup vs baseline: 1.1559x; 1.1559x over previous
#include <cuda_runtime.h>
#include <cstdint>

#define TPB    512
#define TILE_M 128
#define MM     256
#define KK     64
#define ZST    68          // banks 4*grp+tig -> conflict-free frag loads
#define BST    68

// smem layout (float offsets)
#define F_BHI  0
#define F_BLO  (F_BHI + MM * BST)        // 17408
#define F_ZHI  (F_BLO + MM * BST)        // 34816
#define F_ZLO  (F_ZHI + TILE_M * ZST)    // 43520
#define F_B    (F_ZLO + TILE_M * ZST)    // 52224
#define F_PAT  (F_B + MM)                // 52480
#define F_PIV  (F_PAT + MM)              // 52736
#define F_C    (F_PIV + KK)              // 52800
#define F_PSA  (F_C + TILE_M)            // 52928 (4 n-warps x 128 rows)
#define F_PND  (F_PSA + 4 * TILE_M)      // 53440
#define SMEM_FLOATS (F_PND + 4 * TILE_M) // 53952 -> 215808 B

extern __shared__ float sm[];

// tf32 split: hi = rna(x), lo = rna(x - hi)
__device__ __forceinline__ void split_tf32(float x, uint32_t& hi, uint32_t& lo)
{
    asm("cvt.rna.tf32.f32 %0, %1;" : "=r"(hi) : "f"(x));
    float r = x - __uint_as_float(hi);
    asm("cvt.rna.tf32.f32 %0, %1;" : "=r"(lo) : "f"(r));
}

// m16n8k8 tf32 MMA (sm_80 PTX -> legacy HMMA on sm_103)
__device__ __forceinline__ void mma8(float& c0, float& c1, float& c2, float& c3,
                                     uint32_t a0, uint32_t a1, uint32_t a2, uint32_t a3,
                                     uint32_t b0, uint32_t b1)
{
    asm("mma.sync.aligned.m16n8k8.row.col.f32.tf32.tf32.f32 "
        "{%0,%1,%2,%3}, {%4,%5,%6,%7}, {%8,%9}, {%0,%1,%2,%3};"
        : "+f"(c0), "+f"(c1), "+f"(c2), "+f"(c3)
        : "r"(a0), "r"(a1), "r"(a2), "r"(a3), "r"(b0), "r"(b1));
}

// division-free running argmax of alpha = sa/nd
__device__ __forceinline__ void upd(float s, float bcol, float pcol,
                                    float& bsa, float& bnd)
{
    const float sa = s - bcol;
    const float nd = fmaxf(s - pcol, 1e-9f);
    const bool take = (sa >= 0.0f) && (sa * bnd > bsa * nd);
    bsa = take ? sa : bsa;
    bnd = take ? nd : bnd;
}

__global__ void __launch_bounds__(TPB, 1)
constrain_kernel(const float* __restrict__ z,
                 const float* __restrict__ pivot,
                 const float* __restrict__ At,
                 const float* __restrict__ b,
                 float* __restrict__ out,
                 int ntiles)
{
    const int tid = threadIdx.x;
    const int wid = tid >> 5;
    const int lid = tid & 31;
    const int grp = lid >> 2;          // groupID  (0..7)
    const int tig = lid & 3;           // thread-in-group (0..3)
    const int wm  = wid & 3;           // m-warp (0..3): rows wm*32..+31
    const int wn  = wid >> 2;          // n-warp (0..3): cols wn*64..+63
    const int m0  = wm * 32;

    uint32_t* smu = reinterpret_cast<uint32_t*>(sm);

    // ---- stage B = At^T split (once): B[n][k], n-major, stride 68 ----
    #pragma unroll 1
    for (int idx = tid; idx < KK * MM; idx += TPB) {
        const int d = idx >> 8;        // k
        const int n = idx & 255;       // coalesced in n
        uint32_t hi, lo;
        split_tf32(At[idx], hi, lo);
        smu[F_BHI + n * BST + d] = hi;
        smu[F_BLO + n * BST + d] = lo;
    }
    if (tid < KK) sm[F_PIV + tid] = pivot[tid];
    if (tid < MM) sm[F_B + tid] = b[tid];
    __syncthreads();

    // ---- pAt = pivot @ At (fp32, from global; coalesced per d) ----
    if (tid < MM) {
        float a = 0.0f;
        #pragma unroll
        for (int d = 0; d < KK; ++d)
            a = fmaf(sm[F_PIV + d], At[d * MM + tid], a);
        sm[F_PAT + tid] = a;
    }

    // rows this thread reduces: m0+grp, +8, +16, +24
    const int ar0 = (m0 + grp) * ZST;
    const int ar1 = (m0 + 8 + grp) * ZST;
    const int ar2 = (m0 + 16 + grp) * ZST;
    const int ar3 = (m0 + 24 + grp) * ZST;

    // z staging slots: i = tid + q*TPB -> row = i>>4, kq = i&15
    float4 zr[4];

    // ---- preload first tile's z, split, store ----
    {
        const float4* zg4 = reinterpret_cast<const float4*>(z) +
                            (size_t)blockIdx.x * TILE_M * (KK / 4);
        #pragma unroll
        for (int q = 0; q < 4; ++q) {
            const int i   = tid + q * TPB;
            const int row = i >> 4;
            const int kq  = i & 15;
            zr[q] = zg4[i];
            uint32_t h0, l0, h1, l1, h2, l2, h3, l3;
            split_tf32(zr[q].x, h0, l0); split_tf32(zr[q].y, h1, l1);
            split_tf32(zr[q].z, h2, l2); split_tf32(zr[q].w, h3, l3);
            uint32_t* ph = smu + F_ZHI + row * ZST + kq * 4;
            uint32_t* pl = smu + F_ZLO + row * ZST + kq * 4;
            ph[0] = h0; ph[1] = h1; ph[2] = h2; ph[3] = h3;
            pl[0] = l0; pl[1] = l1; pl[2] = l2; pl[3] = l3;
        }
    }
    __syncthreads();

    for (int t = blockIdx.x; t < ntiles; t += gridDim.x) {
        const int tn = t + gridDim.x;

        // ---- prefetch next tile's z into registers (consumed after MMAs) ----
        float4 zf[4];
        if (tn < ntiles) {
            const float4* zg4 = reinterpret_cast<const float4*>(z) +
                                (size_t)tn * TILE_M * (KK / 4);
            #pragma unroll
            for (int q = 0; q < 4; ++q)
                zf[q] = zg4[tid + q * TPB];
        }

        float bsa[4] = {0.0f, 0.0f, 0.0f, 0.0f};
        float bnd[4] = {1.0f, 1.0f, 1.0f, 1.0f};

        #pragma unroll 1
        for (int nci = 0; nci < 2; ++nci) {
            const int nc = nci ^ (wm & 1);     // de-convoy: odd m-warps reversed
            const int nbase = wn * 64 + nc * 32;

            float C[4][8];                     // [ns][tile*4 + reg]
            #pragma unroll
            for (int ns = 0; ns < 4; ++ns)
                #pragma unroll
                for (int r = 0; r < 8; ++r) C[ns][r] = 0.0f;

            #pragma unroll 1
            for (int ks = 0; ks < 8; ++ks) {
                const int k0 = ks * 8 + tig;
                // A fragments: tile0 rows (grp, grp+8), tile1 rows (grp+16, grp+24)
                const uint32_t ah0 = smu[F_ZHI + ar0 + k0];
                const uint32_t ah1 = smu[F_ZHI + ar1 + k0];
                const uint32_t ah2 = smu[F_ZHI + ar0 + k0 + 4];
                const uint32_t ah3 = smu[F_ZHI + ar1 + k0 + 4];
                const uint32_t ah4 = smu[F_ZHI + ar2 + k0];
                const uint32_t ah5 = smu[F_ZHI + ar3 + k0];
                const uint32_t ah6 = smu[F_ZHI + ar2 + k0 + 4];
                const uint32_t ah7 = smu[F_ZHI + ar3 + k0 + 4];
                const uint32_t al0 = smu[F_ZLO + ar0 + k0];
                const uint32_t al1 = smu[F_ZLO + ar1 + k0];
                const uint32_t al2 = smu[F_ZLO + ar0 + k0 + 4];
                const uint32_t al3 = smu[F_ZLO + ar1 + k0 + 4];
                const uint32_t al4 = smu[F_ZLO + ar2 + k0];
                const uint32_t al5 = smu[F_ZLO + ar3 + k0];
                const uint32_t al6 = smu[F_ZLO + ar2 + k0 + 4];
                const uint32_t al7 = smu[F_ZLO + ar3 + k0 + 4];

                // all B fragments for this ks (4 ns groups)
                uint32_t bh0[4], bh1[4], bl0[4], bl1[4];
                #pragma unroll
                for (int ns = 0; ns < 4; ++ns) {
                    const int bn = (nbase + ns * 8 + grp) * BST;
                    bh0[ns] = smu[F_BHI + bn + k0];
                    bh1[ns] = smu[F_BHI + bn + k0 + 4];
                    bl0[ns] = smu[F_BLO + bn + k0];
                    bl1[ns] = smu[F_BLO + bn + k0 + 4];
                }

                // pass-major: 8 independent MMAs per pass, same-C MMAs 8 apart
                #pragma unroll
                for (int ns = 0; ns < 4; ++ns) {   // hh
                    mma8(C[ns][0], C[ns][1], C[ns][2], C[ns][3],
                         ah0, ah1, ah2, ah3, bh0[ns], bh1[ns]);
                    mma8(C[ns][4], C[ns][5], C[ns][6], C[ns][7],
                         ah4, ah5, ah6, ah7, bh0[ns], bh1[ns]);
                }
                #pragma unroll
                for (int ns = 0; ns < 4; ++ns) {   // hl
                    mma8(C[ns][0], C[ns][1], C[ns][2], C[ns][3],
                         ah0, ah1, ah2, ah3, bl0[ns], bl1[ns]);
                    mma8(C[ns][4], C[ns][5], C[ns][6], C[ns][7],
                         ah4, ah5, ah6, ah7, bl0[ns], bl1[ns]);
                }
                #pragma unroll
                for (int ns = 0; ns < 4; ++ns) {   // lh
                    mma8(C[ns][0], C[ns][1], C[ns][2], C[ns][3],
                         al0, al1, al2, al3, bh0[ns], bh1[ns]);
                    mma8(C[ns][4], C[ns][5], C[ns][6], C[ns][7],
                         al4, al5, al6, al7, bh0[ns], bh1[ns]);
                }
            }

            // ---- epilogue for this 32-col chunk ----
            #pragma unroll
            for (int ns = 0; ns < 4; ++ns) {
                const int col0 = nbase + ns * 8 + 2 * tig;
                const float b0 = sm[F_B + col0],   b1 = sm[F_B + col0 + 1];
                const float p0 = sm[F_PAT + col0], p1 = sm[F_PAT + col0 + 1];
                upd(C[ns][0], b0, p0, bsa[0], bnd[0]);   // row grp
                upd(C[ns][1], b1, p1, bsa[0], bnd[0]);
                upd(C[ns][2], b0, p0, bsa[1], bnd[1]);   // row grp+8
                upd(C[ns][3], b1, p1, bsa[1], bnd[1]);
                upd(C[ns][4], b0, p0, bsa[2], bnd[2]);   // row grp+16
                upd(C[ns][5], b1, p1, bsa[2], bnd[2]);
                upd(C[ns][6], b0, p0, bsa[3], bnd[3]);   // row grp+24
                upd(C[ns][7], b1, p1, bsa[3], bnd[3]);
            }
        }

        // reduce across the 4 col-lanes (tig) via bfly xor 1, 2
        #pragma unroll
        for (int r = 0; r < 4; ++r) {
            #pragma unroll
            for (int off = 1; off <= 2; off <<= 1) {
                const float osa = __shfl_xor_sync(0xffffffffu, bsa[r], off);
                const float ond = __shfl_xor_sync(0xffffffffu, bnd[r], off);
                const bool tk = osa * bnd[r] > bsa[r] * ond;
                bsa[r] = tk ? osa : bsa[r];
                bnd[r] = tk ? ond : bnd[r];
            }
        }
        if (tig == 0) {
            const int base = wn * TILE_M + m0 + grp;
            sm[F_PSA + base]      = bsa[0];  sm[F_PND + base]      = bnd[0];
            sm[F_PSA + base + 8]  = bsa[1];  sm[F_PND + base + 8]  = bnd[1];
            sm[F_PSA + base + 16] = bsa[2];  sm[F_PND + base + 16] = bnd[2];
            sm[F_PSA + base + 24] = bsa[3];  sm[F_PND + base + 24] = bnd[3];
        }
        __syncthreads();   // (1) partials ready; all z-smem reads of tile t done

        // ---- merged tail: split z(t+1) into smem (all threads) while
        //      threads 0..127 combine the four n-warp partials ----
        if (tn < ntiles) {
            #pragma unroll
            for (int q = 0; q < 4; ++q) {
                const int i   = tid + q * TPB;
                const int row = i >> 4;
                const int kq  = i & 15;
                uint32_t h0, l0, h1, l1, h2, l2, h3, l3;
                split_tf32(zf[q].x, h0, l0); split_tf32(zf[q].y, h1, l1);
                split_tf32(zf[q].z, h2, l2); split_tf32(zf[q].w, h3, l3);
                uint32_t* ph = smu + F_ZHI + row * ZST + kq * 4;
                uint32_t* pl = smu + F_ZLO + row * ZST + kq * 4;
                ph[0] = h0; ph[1] = h1; ph[2] = h2; ph[3] = h3;
                pl[0] = l0; pl[1] = l1; pl[2] = l2; pl[3] = l3;
            }
        }
        if (tid < TILE_M) {
            float fsa = sm[F_PSA + tid];
            float fnd = sm[F_PND + tid];
            #pragma unroll
            for (int h = 1; h < 4; ++h) {
                const float sa = sm[F_PSA + h * TILE_M + tid];
                const float nd = sm[F_PND + h * TILE_M + tid];
                const bool tk = sa * fnd > fsa * nd;
                fsa = tk ? sa : fsa;
                fnd = tk ? nd : fnd;
            }
            sm[F_C + tid] = fsa / fnd;
        }
        __syncthreads();   // (2) c ready AND z smem for t+1 ready

        // ---- store from registers: out = z + c*(pivot - z), exact z ----
        {
            float4* og4 = reinterpret_cast<float4*>(out) +
                          (size_t)t * TILE_M * (KK / 4);
            const float4* piv4 = reinterpret_cast<const float4*>(sm + F_PIV);
            #pragma unroll
            for (int q = 0; q < 4; ++q) {
                const int i   = tid + q * TPB;
                const int row = i >> 4;
                const int kq  = i & 15;
                const float cc = sm[F_C + row];
                const float4 zz = zr[q];
                const float4 pv = piv4[kq];
                float4 oo;
                oo.x = fmaf(cc, pv.x - zz.x, zz.x);
                oo.y = fmaf(cc, pv.y - zz.y, zz.y);
                oo.z = fmaf(cc, pv.z - zz.z, zz.z);
                oo.w = fmaf(cc, pv.w - zz.w, zz.w);
                og4[i] = oo;
            }
        }

        zr[0] = zf[0]; zr[1] = zf[1]; zr[2] = zf[2]; zr[3] = zf[3];
    }
}

extern "C" void kernel_launch(void* const* d_in, const int* in_sizes, int n_in,
                              void* d_out, int out_size)
{
    const float* z     = (const float*)d_in[0];  // [N, 64]
    const float* pivot = (const float*)d_in[1];  // [64]
    const float* At    = (const float*)d_in[2];  // [64, 256]
    const float* b     = (const float*)d_in[3];  // [256]
    float* out = (float*)d_out;                  // [N, 64]

    const int N = in_sizes[0] / KK;              // 262144
    const int ntiles = N / TILE_M;               // 2048
    const int smem_bytes = SMEM_FLOATS * (int)sizeof(float);  // 215808

    cudaFuncSetAttribute(constrain_kernel,
                         cudaFuncAttributeMaxDynamicSharedMemorySize, smem_bytes);

    int grid = 152;                              // persistent: 1 CTA/SM
    if (grid > ntiles) grid = ntiles;
    constrain_kernel<<<grid, TPB, smem_bytes>>>(z, pivot, At, b, out, ntiles);
}

// round 15
// speedup vs baseline: 1.2361x; 1.0694x over previous
#include <cuda_runtime.h>
#include <cstdint>

#define TPB    512
#define TILE_M 128
#define MM     256
#define KK     64
#define ZST    68          // banks 4*grp+tig -> conflict-free frag loads
#define BST    68

// smem layout (float offsets)
#define F_BHI  0
#define F_BLO  (F_BHI + MM * BST)        // 17408
#define F_ZHI  (F_BLO + MM * BST)        // 34816
#define F_ZLO  (F_ZHI + TILE_M * ZST)    // 43520
#define F_B    (F_ZLO + TILE_M * ZST)    // 52224
#define F_PAT  (F_B + MM)                // 52480
#define F_PIV  (F_PAT + MM)              // 52736
#define F_C    (F_PIV + KK)              // 52800
#define F_PSA  (F_C + TILE_M)            // 52928 (4 n-warps x 128 rows)
#define F_PND  (F_PSA + 4 * TILE_M)      // 53440
#define SMEM_FLOATS (F_PND + 4 * TILE_M) // 53952 -> 215808 B

extern __shared__ float sm[];

// tf32 split: hi = rna(x), lo = rna(x - hi)
__device__ __forceinline__ void split_tf32(float x, uint32_t& hi, uint32_t& lo)
{
    asm("cvt.rna.tf32.f32 %0, %1;" : "=r"(hi) : "f"(x));
    float r = x - __uint_as_float(hi);
    asm("cvt.rna.tf32.f32 %0, %1;" : "=r"(lo) : "f"(r));
}

// m16n8k8 tf32 MMA (sm_80 PTX -> legacy HMMA on sm_103)
__device__ __forceinline__ void mma8(float& c0, float& c1, float& c2, float& c3,
                                     uint32_t a0, uint32_t a1, uint32_t a2, uint32_t a3,
                                     uint32_t b0, uint32_t b1)
{
    asm("mma.sync.aligned.m16n8k8.row.col.f32.tf32.tf32.f32 "
        "{%0,%1,%2,%3}, {%4,%5,%6,%7}, {%8,%9}, {%0,%1,%2,%3};"
        : "+f"(c0), "+f"(c1), "+f"(c2), "+f"(c3)
        : "r"(a0), "r"(a1), "r"(a2), "r"(a3), "r"(b0), "r"(b1));
}

// division-free running argmax of alpha = sa/nd
__device__ __forceinline__ void upd(float s, float bcol, float pcol,
                                    float& bsa, float& bnd)
{
    const float sa = s - bcol;
    const float nd = fmaxf(s - pcol, 1e-9f);
    const bool take = (sa >= 0.0f) && (sa * bnd > bsa * nd);
    bsa = take ? sa : bsa;
    bnd = take ? nd : bnd;
}

__global__ void __launch_bounds__(TPB, 1)
constrain_kernel(const float* __restrict__ z,
                 const float* __restrict__ pivot,
                 const float* __restrict__ At,
                 const float* __restrict__ b,
                 float* __restrict__ out,
                 int ntiles)
{
    const int tid = threadIdx.x;
    const int wid = tid >> 5;
    const int lid = tid & 31;
    const int grp = lid >> 2;          // groupID  (0..7)
    const int tig = lid & 3;           // thread-in-group (0..3)
    const int wm  = wid & 3;           // m-warp (0..3): rows wm*32..+31
    const int wn  = wid >> 2;          // n-warp (0..3): cols wn*64..+63
    const int m0  = wm * 32;

    uint32_t* smu = reinterpret_cast<uint32_t*>(sm);

    // ---- stage B = At^T split (once): B[n][k], n-major, stride 68 ----
    #pragma unroll 1
    for (int idx = tid; idx < KK * MM; idx += TPB) {
        const int d = idx >> 8;        // k
        const int n = idx & 255;       // coalesced in n
        uint32_t hi, lo;
        split_tf32(At[idx], hi, lo);
        smu[F_BHI + n * BST + d] = hi;
        smu[F_BLO + n * BST + d] = lo;
    }
    if (tid < KK) sm[F_PIV + tid] = pivot[tid];
    if (tid < MM) sm[F_B + tid] = b[tid];
    __syncthreads();

    // ---- pAt = pivot @ At (fp32, from global; coalesced per d) ----
    if (tid < MM) {
        float a = 0.0f;
        #pragma unroll
        for (int d = 0; d < KK; ++d)
            a = fmaf(sm[F_PIV + d], At[d * MM + tid], a);
        sm[F_PAT + tid] = a;
    }

    // rows this thread reduces: m0+grp, +8, +16, +24
    const int ar0 = (m0 + grp) * ZST;
    const int ar1 = (m0 + 8 + grp) * ZST;
    const int ar2 = (m0 + 16 + grp) * ZST;
    const int ar3 = (m0 + 24 + grp) * ZST;

    // z staging slots: i = tid + q*TPB -> row = i>>4, kq = i&15
    float4 zr[4];

    // ---- preload first tile's z, split, store ----
    {
        const float4* zg4 = reinterpret_cast<const float4*>(z) +
                            (size_t)blockIdx.x * TILE_M * (KK / 4);
        #pragma unroll
        for (int q = 0; q < 4; ++q) {
            const int i   = tid + q * TPB;
            const int row = i >> 4;
            const int kq  = i & 15;
            zr[q] = zg4[i];
            uint32_t h0, l0, h1, l1, h2, l2, h3, l3;
            split_tf32(zr[q].x, h0, l0); split_tf32(zr[q].y, h1, l1);
            split_tf32(zr[q].z, h2, l2); split_tf32(zr[q].w, h3, l3);
            uint32_t* ph = smu + F_ZHI + row * ZST + kq * 4;
            uint32_t* pl = smu + F_ZLO + row * ZST + kq * 4;
            ph[0] = h0; ph[1] = h1; ph[2] = h2; ph[3] = h3;
            pl[0] = l0; pl[1] = l1; pl[2] = l2; pl[3] = l3;
        }
    }
    __syncthreads();

    for (int t = blockIdx.x; t < ntiles; t += gridDim.x) {
        const int tn = t + gridDim.x;

        float4 zf[4];                  // prefetched mid-loop (short live-range)

        // two independent argmax chains per row (merged before bfly)
        float bsaA[4] = {0.0f, 0.0f, 0.0f, 0.0f};
        float bndA[4] = {1.0f, 1.0f, 1.0f, 1.0f};
        float bsaB[4] = {0.0f, 0.0f, 0.0f, 0.0f};
        float bndB[4] = {1.0f, 1.0f, 1.0f, 1.0f};

        #pragma unroll 1
        for (int nc = 0; nc < 2; ++nc) {       // 32-col chunk of warp's 64 cols
            const int nbase = wn * 64 + nc * 32;

            float C[4][8];                     // [ns][tile*4 + reg]
            #pragma unroll
            for (int ns = 0; ns < 4; ++ns)
                #pragma unroll
                for (int r = 0; r < 8; ++r) C[ns][r] = 0.0f;

            #pragma unroll 1
            for (int ks = 0; ks < 8; ++ks) {
                const int k0 = ks * 8 + tig;
                // A fragments: tile0 rows (grp, grp+8), tile1 rows (grp+16, grp+24)
                const uint32_t ah0 = smu[F_ZHI + ar0 + k0];
                const uint32_t ah1 = smu[F_ZHI + ar1 + k0];
                const uint32_t ah2 = smu[F_ZHI + ar0 + k0 + 4];
                const uint32_t ah3 = smu[F_ZHI + ar1 + k0 + 4];
                const uint32_t ah4 = smu[F_ZHI + ar2 + k0];
                const uint32_t ah5 = smu[F_ZHI + ar3 + k0];
                const uint32_t ah6 = smu[F_ZHI + ar2 + k0 + 4];
                const uint32_t ah7 = smu[F_ZHI + ar3 + k0 + 4];
                const uint32_t al0 = smu[F_ZLO + ar0 + k0];
                const uint32_t al1 = smu[F_ZLO + ar1 + k0];
                const uint32_t al2 = smu[F_ZLO + ar0 + k0 + 4];
                const uint32_t al3 = smu[F_ZLO + ar1 + k0 + 4];
                const uint32_t al4 = smu[F_ZLO + ar2 + k0];
                const uint32_t al5 = smu[F_ZLO + ar3 + k0];
                const uint32_t al6 = smu[F_ZLO + ar2 + k0 + 4];
                const uint32_t al7 = smu[F_ZLO + ar3 + k0 + 4];

                // all B fragments for this ks (4 ns groups)
                uint32_t bh0[4], bh1[4], bl0[4], bl1[4];
                #pragma unroll
                for (int ns = 0; ns < 4; ++ns) {
                    const int bn = (nbase + ns * 8 + grp) * BST;
                    bh0[ns] = smu[F_BHI + bn + k0];
                    bh1[ns] = smu[F_BHI + bn + k0 + 4];
                    bl0[ns] = smu[F_BLO + bn + k0];
                    bl1[ns] = smu[F_BLO + bn + k0 + 4];
                }

                // pass-major: 8 independent MMAs per pass, same-C MMAs 8 apart
                #pragma unroll
                for (int ns = 0; ns < 4; ++ns) {   // hh
                    mma8(C[ns][0], C[ns][1], C[ns][2], C[ns][3],
                         ah0, ah1, ah2, ah3, bh0[ns], bh1[ns]);
                    mma8(C[ns][4], C[ns][5], C[ns][6], C[ns][7],
                         ah4, ah5, ah6, ah7, bh0[ns], bh1[ns]);
                }
                #pragma unroll
                for (int ns = 0; ns < 4; ++ns) {   // hl
                    mma8(C[ns][0], C[ns][1], C[ns][2], C[ns][3],
                         ah0, ah1, ah2, ah3, bl0[ns], bl1[ns]);
                    mma8(C[ns][4], C[ns][5], C[ns][6], C[ns][7],
                         ah4, ah5, ah6, ah7, bl0[ns], bl1[ns]);
                }
                #pragma unroll
                for (int ns = 0; ns < 4; ++ns) {   // lh
                    mma8(C[ns][0], C[ns][1], C[ns][2], C[ns][3],
                         al0, al1, al2, al3, bh0[ns], bh1[ns]);
                    mma8(C[ns][4], C[ns][5], C[ns][6], C[ns][7],
                         al4, al5, al6, al7, bh0[ns], bh1[ns]);
                }
            }

            // ---- prefetch z(t+1) between the two chunks (short live-range) ----
            if (nc == 0 && tn < ntiles) {
                const float4* zg4 = reinterpret_cast<const float4*>(z) +
                                    (size_t)tn * TILE_M * (KK / 4);
                #pragma unroll
                for (int q = 0; q < 4; ++q)
                    zf[q] = zg4[tid + q * TPB];
            }

            // ---- epilogue: two independent chains (ns 0,1 -> A; ns 2,3 -> B) ----
            #pragma unroll
            for (int ns = 0; ns < 4; ++ns) {
                const int col0 = nbase + ns * 8 + 2 * tig;
                const float b0 = sm[F_B + col0],   b1 = sm[F_B + col0 + 1];
                const float p0 = sm[F_PAT + col0], p1 = sm[F_PAT + col0 + 1];
                float* bsa = (ns < 2) ? bsaA : bsaB;
                float* bnd = (ns < 2) ? bndA : bndB;
                upd(C[ns][0], b0, p0, bsa[0], bnd[0]);   // row grp
                upd(C[ns][1], b1, p1, bsa[0], bnd[0]);
                upd(C[ns][2], b0, p0, bsa[1], bnd[1]);   // row grp+8
                upd(C[ns][3], b1, p1, bsa[1], bnd[1]);
                upd(C[ns][4], b0, p0, bsa[2], bnd[2]);   // row grp+16
                upd(C[ns][5], b1, p1, bsa[2], bnd[2]);
                upd(C[ns][6], b0, p0, bsa[3], bnd[3]);   // row grp+24
                upd(C[ns][7], b1, p1, bsa[3], bnd[3]);
            }
        }

        // merge the two chains, then reduce across the 4 col-lanes (tig)
        float bsa[4], bnd[4];
        #pragma unroll
        for (int r = 0; r < 4; ++r) {
            const bool tk = bsaB[r] * bndA[r] > bsaA[r] * bndB[r];
            bsa[r] = tk ? bsaB[r] : bsaA[r];
            bnd[r] = tk ? bndB[r] : bndA[r];
            #pragma unroll
            for (int off = 1; off <= 2; off <<= 1) {
                const float osa = __shfl_xor_sync(0xffffffffu, bsa[r], off);
                const float ond = __shfl_xor_sync(0xffffffffu, bnd[r], off);
                const bool tk2 = osa * bnd[r] > bsa[r] * ond;
                bsa[r] = tk2 ? osa : bsa[r];
                bnd[r] = tk2 ? ond : bnd[r];
            }
        }
        if (tig == 0) {
            const int base = wn * TILE_M + m0 + grp;
            sm[F_PSA + base]      = bsa[0];  sm[F_PND + base]      = bnd[0];
            sm[F_PSA + base + 8]  = bsa[1];  sm[F_PND + base + 8]  = bnd[1];
            sm[F_PSA + base + 16] = bsa[2];  sm[F_PND + base + 16] = bnd[2];
            sm[F_PSA + base + 24] = bsa[3];  sm[F_PND + base + 24] = bnd[3];
        }
        __syncthreads();   // (1) partials ready; all z-smem reads of tile t done

        // combine the four n-warp partials, one divide per row
        if (tid < TILE_M) {
            float fsa = sm[F_PSA + tid];
            float fnd = sm[F_PND + tid];
            #pragma unroll
            for (int h = 1; h < 4; ++h) {
                const float sa = sm[F_PSA + h * TILE_M + tid];
                const float nd = sm[F_PND + h * TILE_M + tid];
                const bool tk = sa * fnd > fsa * nd;
                fsa = tk ? sa : fsa;
                fnd = tk ? nd : fnd;
            }
            sm[F_C + tid] = fsa / fnd;
        }
        __syncthreads();   // (2) c ready

        // ---- store from registers: out = z + c*(pivot - z), exact z ----
        {
            float4* og4 = reinterpret_cast<float4*>(out) +
                          (size_t)t * TILE_M * (KK / 4);
            const float4* piv4 = reinterpret_cast<const float4*>(sm + F_PIV);
            #pragma unroll
            for (int q = 0; q < 4; ++q) {
                const int i   = tid + q * TPB;
                const int row = i >> 4;
                const int kq  = i & 15;
                const float cc = sm[F_C + row];
                const float4 zz = zr[q];
                const float4 pv = piv4[kq];
                float4 oo;
                oo.x = fmaf(cc, pv.x - zz.x, zz.x);
                oo.y = fmaf(cc, pv.y - zz.y, zz.y);
                oo.z = fmaf(cc, pv.z - zz.z, zz.z);
                oo.w = fmaf(cc, pv.w - zz.w, zz.w);
                og4[i] = oo;
            }
        }

        // ---- split prefetched z(t+1) into smem (safe after sync (1)) ----
        if (tn < ntiles) {
            #pragma unroll
            for (int q = 0; q < 4; ++q) {
                const int i   = tid + q * TPB;
                const int row = i >> 4;
                const int kq  = i & 15;
                uint32_t h0, l0, h1, l1, h2, l2, h3, l3;
                split_tf32(zf[q].x, h0, l0); split_tf32(zf[q].y, h1, l1);
                split_tf32(zf[q].z, h2, l2); split_tf32(zf[q].w, h3, l3);
                uint32_t* ph = smu + F_ZHI + row * ZST + kq * 4;
                uint32_t* pl = smu + F_ZLO + row * ZST + kq * 4;
                ph[0] = h0; ph[1] = h1; ph[2] = h2; ph[3] = h3;
                pl[0] = l0; pl[1] = l1; pl[2] = l2; pl[3] = l3;
            }
        }
        __syncthreads();   // (3) z smem for t+1 ready

        zr[0] = zf[0]; zr[1] = zf[1]; zr[2] = zf[2]; zr[3] = zf[3];
    }
}

extern "C" void kernel_launch(void* const* d_in, const int* in_sizes, int n_in,
                              void* d_out, int out_size)
{
    const float* z     = (const float*)d_in[0];  // [N, 64]
    const float* pivot = (const float*)d_in[1];  // [64]
    const float* At    = (const float*)d_in[2];  // [64, 256]
    const float* b     = (const float*)d_in[3];  // [256]
    float* out = (float*)d_out;                  // [N, 64]

    const int N = in_sizes[0] / KK;              // 262144
    const int ntiles = N / TILE_M;               // 2048
    const int smem_bytes = SMEM_FLOATS * (int)sizeof(float);  // 215808

    cudaFuncSetAttribute(constrain_kernel,
                         cudaFuncAttributeMaxDynamicSharedMemorySize, smem_bytes);

    int grid = 152;                              // persistent: 1 CTA/SM
    if (grid > ntiles) grid = ntiles;
    constrain_kernel<<<grid, TPB, smem_bytes>>>(z, pivot, At, b, out, ntiles);
}